// round 13
// baseline (speedup 1.0000x reference)
#include <cuda_runtime.h>
#include <cuda_bf16.h>
#include <cstdint>

// Problem constants
#define BB 4
#define TT 2048
#define DD 1024
#define HH 16
#define HD 64
// M = B*T = 8192 rows

// Scratch (device globals: no allocation allowed)
__device__ float g_qkv[(size_t)BB * TT * 3 * DD];   // [8192, 3072]
__device__ float g_y[(size_t)BB * TT * DD];          // [8192, 1024]
// Pre-permuted tf32 operands (tile-layout: [kk][row][16 k-permuted])
__device__ float g_xp[(size_t)BB * TT * DD];         // x permuted   (32 MB)
__device__ float g_yp[(size_t)BB * TT * DD];         // y permuted   (32 MB)
__device__ float g_wap[(size_t)DD * 3 * DD];         // W_attn perm  (12 MB)
__device__ float g_wpp[(size_t)DD * DD];             // W_proj perm  (4 MB)

// ---------------------------------------------------------------------------
// tf32 helpers (portable PTX: works on compute_103 target, no 'a' feature)
// ---------------------------------------------------------------------------
__device__ __forceinline__ uint32_t to_tf32(float x) {
    uint32_t r;
    asm("cvt.rna.tf32.f32 %0, %1;" : "=r"(r) : "f"(x));
    return r;
}

// mma.sync m16n8k8 tf32: D(16x8,f32) += A(16x8,tf32) * B(8x8,tf32)
__device__ __forceinline__ void mma_tf32(float* d,
                                         uint32_t a0, uint32_t a1, uint32_t a2, uint32_t a3,
                                         uint32_t b0, uint32_t b1) {
    asm volatile(
        "mma.sync.aligned.m16n8k8.row.col.f32.tf32.tf32.f32 "
        "{%0,%1,%2,%3}, {%4,%5,%6,%7}, {%8,%9}, {%0,%1,%2,%3};"
        : "+f"(d[0]), "+f"(d[1]), "+f"(d[2]), "+f"(d[3])
        : "r"(a0), "r"(a1), "r"(a2), "r"(a3), "r"(b0), "r"(b1));
}

__device__ __forceinline__ uint32_t smem_u32(const void* p) {
    uint32_t a;
    asm("{ .reg .u64 t; cvta.to.shared.u64 t, %1; cvt.u32.u64 %0, t; }"
        : "=r"(a) : "l"(p));
    return a;
}

__device__ __forceinline__ void cp16(uint32_t dst, const void* src) {
    asm volatile("cp.async.cg.shared.global [%0], [%1], 16;"
                 :: "r"(dst), "l"(src) : "memory");
}
#define CP_COMMIT() asm volatile("cp.async.commit_group;" ::: "memory")
#define CP_WAIT2()  asm volatile("cp.async.wait_group 2;" ::: "memory")

// ---------------------------------------------------------------------------
// Fast exp2: p = 2^y for y <= 0 (clamped at -126). 5-FFMA Taylor, |f|<=0.5.
// ---------------------------------------------------------------------------
__device__ __forceinline__ float fast_exp2(float y) {
    y = fmaxf(y, -126.0f);
    int ei = __float2int_rn(y);
    float f = y - (float)ei;
    float p = 0.0013333558146428443f;
    p = fmaf(p, f, 0.009618129107628477f);
    p = fmaf(p, f, 0.05550410866482158f);
    p = fmaf(p, f, 0.2402265069591007f);
    p = fmaf(p, f, 0.6931471805599453f);
    p = fmaf(p, f, 1.0f);
    return p * __int_as_float((ei + 127) << 23);
}

// ===========================================================================
// Pre-permute kernels: write tf32-rounded, k-permuted tile layouts.
// Logical layout: dst[((kk * R) + row) * 16 + 4*g + e]  holds  src_k = 4*e + g
// (i.e. group g = {k=g, 4+g, 8+g, 12+g}) — exactly what the GEMM smem tile
// and its LDS.128 fragment loads expect.
// ===========================================================================
__global__ __launch_bounds__(256)
void permute_a(const float* __restrict__ src, float* __restrict__ dst, int R) {
    int gidx = blockIdx.x * 256 + threadIdx.x;   // = r*64 + kk
    int r = gidx >> 6, kk = gidx & 63;
    const float4* s = reinterpret_cast<const float4*>(src + (size_t)r * 1024 + kk * 16);
    float4 v0 = s[0], v1 = s[1], v2 = s[2], v3 = s[3];   // vj[g] = k = 4j+g
    uint4* d = reinterpret_cast<uint4*>(dst + ((size_t)kk * R + r) * 16);
    uint4 o0, o1, o2, o3;
    o0.x = to_tf32(v0.x); o0.y = to_tf32(v1.x); o0.z = to_tf32(v2.x); o0.w = to_tf32(v3.x);
    o1.x = to_tf32(v0.y); o1.y = to_tf32(v1.y); o1.z = to_tf32(v2.y); o1.w = to_tf32(v3.y);
    o2.x = to_tf32(v0.z); o2.y = to_tf32(v1.z); o2.z = to_tf32(v2.z); o2.w = to_tf32(v3.z);
    o3.x = to_tf32(v0.w); o3.y = to_tf32(v1.w); o3.z = to_tf32(v2.w); o3.w = to_tf32(v3.w);
    d[0] = o0; d[1] = o1; d[2] = o2; d[3] = o3;
}

// W: [1024, N] row-major -> dst[((kk*N)+n)*16 + 4g+e] = W[16kk + 4e+g][n]
__global__ __launch_bounds__(256)
void permute_b(const float* __restrict__ W, float* __restrict__ dst, int N) {
    int n = blockIdx.x * 256 + threadIdx.x;
    int kk = blockIdx.y;
    const float* w = W + (size_t)(kk * 16) * N + n;
    float v[16];
#pragma unroll
    for (int k = 0; k < 16; k++) v[k] = w[(size_t)k * N];
    uint4* d = reinterpret_cast<uint4*>(dst + ((size_t)kk * N + n) * 16);
#pragma unroll
    for (int g = 0; g < 4; g++) {
        uint4 o;
        o.x = to_tf32(v[g]);      o.y = to_tf32(v[4 + g]);
        o.z = to_tf32(v[8 + g]);  o.w = to_tf32(v[12 + g]);
        d[g] = o;
    }
}

// ===========================================================================
// Tensor-core GEMM via mma.sync tf32 on pre-permuted operands.
// C[M,N] = A @ B; CTA tile 128x256, 512 threads (16 warps 4x4), warp 32x64.
// 4-stage cp.async pipeline; one __syncthreads per stage. K = 1024.
// ===========================================================================
#define STAGES 4
#define NSTAGE 64                     // 1024 / 16
#define GEMM_SMEM (STAGES * (128 * 16 + 256 * 16) * 4)   // 98304 bytes

__global__ __launch_bounds__(512, 1)
void mma_gemm(const float* __restrict__ Ap, const float* __restrict__ Bp,
              float* __restrict__ C, int M, int N) {
    extern __shared__ float smg[];
    float* const AsBase = smg;                        // STAGES * 2048 floats
    float* const BsBase = smg + STAGES * 128 * 16;    // STAGES * 4096 floats
    const uint32_t smem_base = smem_u32(smg);

    const int tid = threadIdx.x;
    const int lane = tid & 31;
    const int wid = tid >> 5;       // 0..15
    const int wm = wid >> 2;        // 0..3 (M, 32 rows each)
    const int wn = wid & 3;         // 0..3 (N, 64 cols each)
    const int row0 = blockIdx.y * 128;
    const int col0 = blockIdx.x * 256;
    const int gid = lane >> 2;      // 0..7
    const int tig = lane & 3;       // 0..3

    // ---- cp.async chunk mapping (per thread: 1 A chunk + 2 B chunks) ----
    const int cr = tid >> 2;                   // chunk row 0..127
    const int cg = tid & 3;                    // logical group 0..3
    const int csw = (tid >> 3) & 3;            // (cr>>1)&3 (same for cr+128)
    const uint32_t dst_off = (uint32_t)(cr * 16 + ((cg ^ csw) << 2)) * 4;  // bytes

    const float* a_src  = Ap + ((size_t)(row0 + cr)) * 16 + cg * 4;
    const float* b_src0 = Bp + ((size_t)(col0 + cr)) * 16 + cg * 4;
    const float* b_src1 = b_src0 + (size_t)128 * 16;
    const size_t a_step = (size_t)M * 16;
    const size_t b_step = (size_t)N * 16;

    auto issue = [&](int s, int kstage) {
        uint32_t a_dst = smem_base + (uint32_t)s * 8192 + dst_off;
        uint32_t b_dst = smem_base + (uint32_t)STAGES * 8192 + (uint32_t)s * 16384 + dst_off;
        cp16(a_dst, a_src + (size_t)kstage * a_step);
        cp16(b_dst, b_src0 + (size_t)kstage * b_step);
        cp16(b_dst + 8192, b_src1 + (size_t)kstage * b_step);
    };

    // ---- fragment base offsets (swizzle invariant across mf/nf) ----
    const int ra_base = wm * 32 + gid;
    const int aFragBase = ra_base * 16 + ((tig ^ ((ra_base >> 1) & 3)) << 2);
    const int nb = wn * 64 + gid;
    const int bFragBase = nb * 16 + ((tig ^ ((nb >> 1) & 3)) << 2);

    float acc[2][8][4];
#pragma unroll
    for (int mf = 0; mf < 2; mf++)
#pragma unroll
        for (int nf = 0; nf < 8; nf++)
#pragma unroll
            for (int i = 0; i < 4; i++) acc[mf][nf][i] = 0.0f;

    auto compute = [&](int s) {
        const float* As_ = AsBase + s * 2048;
        const float* Bs_ = BsBase + s * 4096;
        float4 av0[2], av1[2];
#pragma unroll
        for (int mf = 0; mf < 2; mf++) {
            av0[mf] = *reinterpret_cast<const float4*>(&As_[aFragBase + 256 * mf]);
            av1[mf] = *reinterpret_cast<const float4*>(&As_[aFragBase + 256 * mf + 128]);
        }
#pragma unroll
        for (int nf = 0; nf < 8; nf++) {
            float4 bv = *reinterpret_cast<const float4*>(&Bs_[bFragBase + 128 * nf]);
#pragma unroll
            for (int mf = 0; mf < 2; mf++) {
                mma_tf32(acc[mf][nf],
                         __float_as_uint(av0[mf].x), __float_as_uint(av1[mf].x),
                         __float_as_uint(av0[mf].y), __float_as_uint(av1[mf].y),
                         __float_as_uint(bv.x), __float_as_uint(bv.y));
                mma_tf32(acc[mf][nf],
                         __float_as_uint(av0[mf].z), __float_as_uint(av1[mf].z),
                         __float_as_uint(av0[mf].w), __float_as_uint(av1[mf].w),
                         __float_as_uint(bv.z), __float_as_uint(bv.w));
            }
        }
    };

    // ---- prologue: stages 0..2 in flight ----
#pragma unroll
    for (int s = 0; s < STAGES - 1; s++) {
        issue(s, s);
        CP_COMMIT();
    }

    // ---- mainloop: one barrier per stage ----
#pragma unroll 4
    for (int kk = 0; kk < NSTAGE; kk++) {
        CP_WAIT2();                       // stage kk complete (per thread)
        __syncthreads();                  // visible to all; slot (kk-1)%4 free
        if (kk + STAGES - 1 < NSTAGE)
            issue((kk + STAGES - 1) & (STAGES - 1), kk + STAGES - 1);
        CP_COMMIT();
        compute(kk & (STAGES - 1));
    }

    // ---- epilogue ----
#pragma unroll
    for (int mf = 0; mf < 2; mf++) {
#pragma unroll
        for (int nf = 0; nf < 8; nf++) {
            int r = row0 + wm * 32 + mf * 16 + gid;
            int c = col0 + wn * 64 + nf * 8 + tig * 2;
            float2 lo = make_float2(acc[mf][nf][0], acc[mf][nf][1]);
            float2 hi = make_float2(acc[mf][nf][2], acc[mf][nf][3]);
            *reinterpret_cast<float2*>(&C[(size_t)r * N + c]) = lo;
            *reinterpret_cast<float2*>(&C[(size_t)(r + 8) * N + c]) = hi;
        }
    }
}

// ===========================================================================
// Flash attention via mma.sync tf32 (causal). Unchanged from round 9 (passes).
// ===========================================================================
#define ATS 68   // smem row stride (floats)

__global__ __launch_bounds__(256, 1)
void flash_attn_mma(const float* __restrict__ qkv, float* __restrict__ y) {
    extern __shared__ float sm[];
    float* Ks = sm;                  // [64][68]
    float* Vs = sm + 64 * ATS;       // [64][68]
    float* Ps = sm + 2 * 64 * ATS;   // [128][68] (also Q staging)

    const int tid = threadIdx.x;
    const int lane = tid & 31;
    const int w = tid >> 5;          // 0..7
    const int gid = lane >> 2;       // 0..7
    const int tig = lane & 3;        // 0..3
    const int bh = blockIdx.x;
    const int b = bh >> 4;
    const int h = bh & 15;
    const int q0 = (15 - (int)blockIdx.y) * 128;   // heavy blocks first
    const int row3 = 3 * DD;

    const float* qkv_b = qkv + (size_t)(b * TT) * row3;
    const float* qgm = qkv_b + h * HD;
    const float* kgm = qkv_b + DD + h * HD;
    const float* vgm = qkv_b + 2 * DD + h * HD;

    // ---- Stage Q tile into Ps, then build per-warp Q fragments (2x split) --
#pragma unroll
    for (int i = 0; i < 8; i++) {
        int idx = tid + i * 256;
        int r = idx >> 4, c4 = idx & 15;
        float4 v = *reinterpret_cast<const float4*>(
            qgm + (size_t)(q0 + r) * row3 + c4 * 4);
        *reinterpret_cast<float4*>(Ps + r * ATS + c4 * 4) = v;
    }
    __syncthreads();

    const float scale2 = 0.125f * 1.4426950408889634f;
    uint32_t qhi[8][4], qlo[8][4];
    {
        const int r0 = w * 16 + gid;
#pragma unroll
        for (int c = 0; c < 8; c++) {
            float v0 = Ps[r0 * ATS + 8 * c + tig] * scale2;          // a0
            float v1 = Ps[(r0 + 8) * ATS + 8 * c + tig] * scale2;    // a1
            float v2 = Ps[r0 * ATS + 8 * c + tig + 4] * scale2;      // a2
            float v3 = Ps[(r0 + 8) * ATS + 8 * c + tig + 4] * scale2;// a3
            qhi[c][0] = to_tf32(v0); qlo[c][0] = to_tf32(v0 - __uint_as_float(qhi[c][0]));
            qhi[c][1] = to_tf32(v1); qlo[c][1] = to_tf32(v1 - __uint_as_float(qhi[c][1]));
            qhi[c][2] = to_tf32(v2); qlo[c][2] = to_tf32(v2 - __uint_as_float(qhi[c][2]));
            qhi[c][3] = to_tf32(v3); qlo[c][3] = to_tf32(v3 - __uint_as_float(qhi[c][3]));
        }
    }
    __syncthreads();

    float yacc[8][4];
#pragma unroll
    for (int j = 0; j < 8; j++)
#pragma unroll
        for (int e = 0; e < 4; e++) yacc[j][e] = 0.0f;
    float m0 = -1e30f, m1 = -1e30f, l0 = 0.0f, l1 = 0.0f;

    const int ntiles = q0 / 64 + 2;
    float4 kreg[4], vreg[4];

    auto ldg_kv = [&](int tn) {
        int kv0 = tn * 64;
#pragma unroll
        for (int i = 0; i < 4; i++) {
            int idx = tid + i * 256;
            int r = idx >> 4, c4 = idx & 15;
            kreg[i] = *reinterpret_cast<const float4*>(
                kgm + (size_t)(kv0 + r) * row3 + c4 * 4);
            vreg[i] = *reinterpret_cast<const float4*>(
                vgm + (size_t)(kv0 + r) * row3 + c4 * 4);
        }
    };
    auto sts_kv = [&]() {
#pragma unroll
        for (int i = 0; i < 4; i++) {
            int idx = tid + i * 256;
            int r = idx >> 4, c4 = idx & 15;
            uint4 tk, tv;
            tk.x = to_tf32(kreg[i].x); tk.y = to_tf32(kreg[i].y);
            tk.z = to_tf32(kreg[i].z); tk.w = to_tf32(kreg[i].w);
            tv.x = to_tf32(vreg[i].x); tv.y = to_tf32(vreg[i].y);
            tv.z = to_tf32(vreg[i].z); tv.w = to_tf32(vreg[i].w);
            *reinterpret_cast<uint4*>(Ks + r * ATS + c4 * 4) = tk;
            *reinterpret_cast<uint4*>(Vs + r * ATS + c4 * 4) = tv;
        }
    };

    ldg_kv(0);
    sts_kv();
    __syncthreads();

    const int pr0 = (w * 16 + gid) * ATS;

    for (int t = 0; t < ntiles; t++) {
        const int kv0 = t * 64;
        if (t + 1 < ntiles) ldg_kv(t + 1);

        const bool active = (kv0 <= q0 + w * 16 + 15);
        if (active) {
            // ---- QK^T (2xTF32: q_hi*K + q_lo*K) ----
            float sacc[8][4];
#pragma unroll
            for (int j = 0; j < 8; j++)
#pragma unroll
                for (int e = 0; e < 4; e++) sacc[j][e] = 0.0f;
#pragma unroll
            for (int j = 0; j < 8; j++) {
                const int kr = (8 * j + gid) * ATS;
#pragma unroll
                for (int c = 0; c < 8; c++) {
                    uint32_t b0 = __float_as_uint(Ks[kr + 8 * c + tig]);
                    uint32_t b1 = __float_as_uint(Ks[kr + 8 * c + tig + 4]);
                    mma_tf32(sacc[j], qhi[c][0], qhi[c][1], qhi[c][2], qhi[c][3], b0, b1);
                    mma_tf32(sacc[j], qlo[c][0], qlo[c][1], qlo[c][2], qlo[c][3], b0, b1);
                }
            }

            // ---- causal mask (only last two tiles) ----
            if (t >= ntiles - 2) {
                const int r0g = q0 + w * 16 + gid;
#pragma unroll
                for (int j = 0; j < 8; j++) {
                    int col = kv0 + 8 * j + 2 * tig;
                    if (col > r0g)         sacc[j][0] = -1e30f;
                    if (col + 1 > r0g)     sacc[j][1] = -1e30f;
                    if (col > r0g + 8)     sacc[j][2] = -1e30f;
                    if (col + 1 > r0g + 8) sacc[j][3] = -1e30f;
                }
            }

            // ---- online softmax ----
            float mt0 = -1e30f, mt1 = -1e30f;
#pragma unroll
            for (int j = 0; j < 8; j++) {
                mt0 = fmaxf(mt0, fmaxf(sacc[j][0], sacc[j][1]));
                mt1 = fmaxf(mt1, fmaxf(sacc[j][2], sacc[j][3]));
            }
            mt0 = fmaxf(mt0, __shfl_xor_sync(0xffffffffu, mt0, 1));
            mt0 = fmaxf(mt0, __shfl_xor_sync(0xffffffffu, mt0, 2));
            mt1 = fmaxf(mt1, __shfl_xor_sync(0xffffffffu, mt1, 1));
            mt1 = fmaxf(mt1, __shfl_xor_sync(0xffffffffu, mt1, 2));

            float mn0 = fmaxf(m0, mt0), mn1 = fmaxf(m1, mt1);
            float cr0 = fast_exp2(m0 - mn0), cr1 = fast_exp2(m1 - mn1);
            m0 = mn0; m1 = mn1;
#pragma unroll
            for (int j = 0; j < 8; j++) {
                yacc[j][0] *= cr0; yacc[j][1] *= cr0;
                yacc[j][2] *= cr1; yacc[j][3] *= cr1;
            }

            float rs0 = 0.0f, rs1 = 0.0f;
#pragma unroll
            for (int j = 0; j < 8; j++) {
                float p0 = fast_exp2(sacc[j][0] - m0);
                float p1 = fast_exp2(sacc[j][1] - m0);
                float p2 = fast_exp2(sacc[j][2] - m1);
                float p3 = fast_exp2(sacc[j][3] - m1);
                rs0 += p0 + p1; rs1 += p2 + p3;
                float2 lo, hi;
                lo.x = __uint_as_float(to_tf32(p0)); lo.y = __uint_as_float(to_tf32(p1));
                hi.x = __uint_as_float(to_tf32(p2)); hi.y = __uint_as_float(to_tf32(p3));
                *reinterpret_cast<float2*>(Ps + pr0 + 8 * j + 2 * tig) = lo;
                *reinterpret_cast<float2*>(Ps + pr0 + 8 * ATS + 8 * j + 2 * tig) = hi;
            }
            rs0 += __shfl_xor_sync(0xffffffffu, rs0, 1);
            rs0 += __shfl_xor_sync(0xffffffffu, rs0, 2);
            rs1 += __shfl_xor_sync(0xffffffffu, rs1, 1);
            rs1 += __shfl_xor_sync(0xffffffffu, rs1, 2);
            l0 = l0 * cr0 + rs0;
            l1 = l1 * cr1 + rs1;

            __syncwarp();

            // ---- P @ V ----
#pragma unroll
            for (int c = 0; c < 8; c++) {
                uint32_t a0 = __float_as_uint(Ps[pr0 + 8 * c + tig]);
                uint32_t a1 = __float_as_uint(Ps[pr0 + 8 * ATS + 8 * c + tig]);
                uint32_t a2 = __float_as_uint(Ps[pr0 + 8 * c + tig + 4]);
                uint32_t a3 = __float_as_uint(Ps[pr0 + 8 * ATS + 8 * c + tig + 4]);
                const int vr = (8 * c + tig) * ATS;
#pragma unroll
                for (int j = 0; j < 8; j++) {
                    uint32_t b0 = __float_as_uint(Vs[vr + 8 * j + gid]);
                    uint32_t b1 = __float_as_uint(Vs[vr + 4 * ATS + 8 * j + gid]);
                    mma_tf32(yacc[j], a0, a1, a2, a3, b0, b1);
                }
            }
        }

        __syncthreads();                 // all warps done with Ks/Vs
        if (t + 1 < ntiles) {
            sts_kv();
            __syncthreads();             // tiles visible before next compute
        }
    }

    // ---- epilogue: normalize, store ----
    const float inv0 = 1.0f / l0;
    const float inv1 = 1.0f / l1;
    const int r0 = q0 + w * 16 + gid;
#pragma unroll
    for (int j = 0; j < 8; j++) {
        int col = h * HD + 8 * j + 2 * tig;
        float2 lo = make_float2(yacc[j][0] * inv0, yacc[j][1] * inv0);
        float2 hi = make_float2(yacc[j][2] * inv1, yacc[j][3] * inv1);
        *reinterpret_cast<float2*>(y + (size_t)(b * TT + r0) * DD + col) = lo;
        *reinterpret_cast<float2*>(y + (size_t)(b * TT + r0 + 8) * DD + col) = hi;
    }
}

// ---------------------------------------------------------------------------
// kernel_launch
// ---------------------------------------------------------------------------
extern "C" void kernel_launch(void* const* d_in, const int* in_sizes, int n_in,
                              void* d_out, int out_size) {
    const float* x  = (const float*)d_in[0];   // [4,2048,1024]
    const float* Wa = (const float*)d_in[1];   // [1024,3072]
    const float* Wp = (const float*)d_in[2];   // [1024,1024]
    float* out = (float*)d_out;                // [4,2048,1024]

    float *qkv_ptr = nullptr, *y_ptr = nullptr;
    float *xp = nullptr, *yp = nullptr, *wap = nullptr, *wpp = nullptr;
    cudaGetSymbolAddress((void**)&qkv_ptr, g_qkv);
    cudaGetSymbolAddress((void**)&y_ptr, g_y);
    cudaGetSymbolAddress((void**)&xp, g_xp);
    cudaGetSymbolAddress((void**)&yp, g_yp);
    cudaGetSymbolAddress((void**)&wap, g_wap);
    cudaGetSymbolAddress((void**)&wpp, g_wpp);

    const int M = BB * TT;                     // 8192

    cudaFuncSetAttribute(mma_gemm, cudaFuncAttributeMaxDynamicSharedMemorySize,
                         GEMM_SMEM);

    // 0) Pre-permute + tf32-round inputs
    permute_a<<<M * 64 / 256, 256>>>(x, xp, M);
    permute_b<<<dim3(3 * DD / 256, 64), 256>>>(Wa, wap, 3 * DD);
    permute_b<<<dim3(DD / 256, 64), 256>>>(Wp, wpp, DD);

    // 1) QKV GEMM: [8192,1024] @ [1024,3072] -> g_qkv   (cp.async + mma tf32)
    {
        dim3 grid(3 * DD / 256, M / 128);
        mma_gemm<<<grid, 512, GEMM_SMEM>>>(xp, wap, qkv_ptr, M, 3 * DD);
    }

    // 2) Flash attention (mma.sync tf32) -> g_y
    {
        const int smem_bytes = (2 * 64 * ATS + 128 * ATS) * (int)sizeof(float); // 69632
        cudaFuncSetAttribute(flash_attn_mma,
                             cudaFuncAttributeMaxDynamicSharedMemorySize, smem_bytes);
        dim3 grid(BB * HH, TT / 128);
        flash_attn_mma<<<grid, 256, smem_bytes>>>(qkv_ptr, y_ptr);
    }

    // 2b) Permute attention output for the proj GEMM
    permute_a<<<M * 64 / 256, 256>>>(y_ptr, yp, M);

    // 3) Proj GEMM: [8192,1024] @ [1024,1024] -> out    (cp.async + mma tf32)
    {
        dim3 grid(DD / 256, M / 128);
        mma_gemm<<<grid, 512, GEMM_SMEM>>>(yp, wpp, out, M, DD);
    }
}